// round 4
// baseline (speedup 1.0000x reference)
#include <cuda_runtime.h>

// PositionwiseMaxPool2D: x [32,128,128,64] f32 NHWC -> out [32,64,64,64]
// For each 2x2 window, pick the position with max channel-sumsq, copy its
// 64-channel vector.
//
// R2: default (caching) loads — R1 showed __ldcs regresses DRAM throughput.
// 2 output pixels per thread (adjacent in ow): 8 front-batched LDG.128 per
// thread (MLP_p1=8), 1KB contiguous span per input row per 16-lane group,
// half the grid (fewer waves, smaller tail).

#define B_DIM 32
#define H_DIM 128
#define W_DIM 128
#define C_DIM 64
#define OH 64
#define OW 64
#define LANES_PER_PIX 16   // 64 channels / 4 per float4
#define C4 (C_DIM / 4)     // 16 float4 per pixel

__global__ __launch_bounds__(256)
void pos_maxpool2d_kernel(const float* __restrict__ x, float* __restrict__ out) {
    const int tid  = blockIdx.x * blockDim.x + threadIdx.x;
    const int lane = tid & (LANES_PER_PIX - 1);
    const int opp  = tid >> 4;               // output-pixel-pair index, < 32*64*32

    const int owp = opp & (OW / 2 - 1);      // pair of adjacent output cols
    const int oh  = (opp >> 5) & (OH - 1);
    const int b   = opp >> 11;

    const float4* __restrict__ xv = reinterpret_cast<const float4*>(x);

    // Input base: row 2*oh, col 4*owp. C4=16 float4 per input pixel.
    const int base = ((b * H_DIM + 2 * oh) * W_DIM + 4 * owp) * C4;
    const int rs   = W_DIM * C4;             // one input row in float4 units

    // 8 loads, front-batched. Pixel0 window = input cols {0,1}, pixel1 = {2,3}.
    const float4 a0 = xv[base + lane];            // r0 c0  (pix0)
    const float4 a1 = xv[base + C4 + lane];       // r0 c1  (pix0)
    const float4 a2 = xv[base + 2 * C4 + lane];   // r0 c2  (pix1)
    const float4 a3 = xv[base + 3 * C4 + lane];   // r0 c3  (pix1)
    const float4 b0 = xv[base + rs + lane];           // r1 c0  (pix0)
    const float4 b1 = xv[base + rs + C4 + lane];      // r1 c1  (pix0)
    const float4 b2 = xv[base + rs + 2 * C4 + lane];  // r1 c2  (pix1)
    const float4 b3 = xv[base + rs + 3 * C4 + lane];  // r1 c3  (pix1)

    float n0 = a0.x * a0.x + a0.y * a0.y + a0.z * a0.z + a0.w * a0.w;
    float n1 = a1.x * a1.x + a1.y * a1.y + a1.z * a1.z + a1.w * a1.w;
    float n2 = a2.x * a2.x + a2.y * a2.y + a2.z * a2.z + a2.w * a2.w;
    float n3 = a3.x * a3.x + a3.y * a3.y + a3.z * a3.z + a3.w * a3.w;
    float m0 = b0.x * b0.x + b0.y * b0.y + b0.z * b0.z + b0.w * b0.w;
    float m1 = b1.x * b1.x + b1.y * b1.y + b1.z * b1.z + b1.w * b1.w;
    float m2 = b2.x * b2.x + b2.y * b2.y + b2.z * b2.z + b2.w * b2.w;
    float m3 = b3.x * b3.x + b3.y * b3.y + b3.z * b3.z + b3.w * b3.w;

    // Butterfly reduction within each 16-lane group (subset of a warp).
    // All lanes end with bitwise-identical sums.
    #pragma unroll
    for (int s = LANES_PER_PIX / 2; s > 0; s >>= 1) {
        n0 += __shfl_xor_sync(0xffffffffu, n0, s);
        n1 += __shfl_xor_sync(0xffffffffu, n1, s);
        n2 += __shfl_xor_sync(0xffffffffu, n2, s);
        n3 += __shfl_xor_sync(0xffffffffu, n3, s);
        m0 += __shfl_xor_sync(0xffffffffu, m0, s);
        m1 += __shfl_xor_sync(0xffffffffu, m1, s);
        m2 += __shfl_xor_sync(0xffffffffu, m2, s);
        m3 += __shfl_xor_sync(0xffffffffu, m3, s);
    }

    // Pixel 0: candidates (n0:a0, n1:a1, m0:b0, m1:b1) in K-order 0..3.
    // First-occurrence argmax via strict > (matches jnp.argmax).
    {
        int   idx  = 0;
        float best = n0;
        if (n1 > best) { best = n1; idx = 1; }
        if (m0 > best) { best = m0; idx = 2; }
        if (m1 > best) { best = m1; idx = 3; }
        float4 w = a0;
        if (idx == 1) w = a1;
        if (idx == 2) w = b0;
        if (idx == 3) w = b1;
        const int op0 = ((b * OH + oh) * OW + 2 * owp);
        reinterpret_cast<float4*>(out)[op0 * C4 + lane] = w;
    }
    // Pixel 1: candidates (n2:a2, n3:a3, m2:b2, m3:b3).
    {
        int   idx  = 0;
        float best = n2;
        if (n3 > best) { best = n3; idx = 1; }
        if (m2 > best) { best = m2; idx = 2; }
        if (m3 > best) { best = m3; idx = 3; }
        float4 w = a2;
        if (idx == 1) w = a3;
        if (idx == 2) w = b2;
        if (idx == 3) w = b3;
        const int op1 = ((b * OH + oh) * OW + 2 * owp + 1);
        reinterpret_cast<float4*>(out)[op1 * C4 + lane] = w;
    }
}

extern "C" void kernel_launch(void* const* d_in, const int* in_sizes, int n_in,
                              void* d_out, int out_size) {
    const float* x = (const float*)d_in[0];
    float* out = (float*)d_out;
    const int total_threads = B_DIM * OH * (OW / 2) * LANES_PER_PIX; // 1,048,576
    const int block = 256;
    const int grid = total_threads / block;                          // 4096
    pos_maxpool2d_kernel<<<grid, block>>>(x, out);
}

// round 5
// speedup vs baseline: 1.0011x; 1.0011x over previous
#include <cuda_runtime.h>

// PositionwiseMaxPool2D: x [32,128,128,64] f32 NHWC -> out [32,64,64,64]
// For each 2x2 window, pick the position with max channel-sumsq, copy its
// 64-channel vector.
//
// R4: persistent single-wave grid. 1024 blocks x 256 threads are all
// resident at once (8 warps/SM-worth of CTAs across 148-152 SMs); each
// thread processes 8 output pixels via grid-stride. No wave transitions,
// no drain tail; unroll-2 lets loads of iter i+1 overlap stores of iter i.
// Body identical to R0 (best measured config): 16 lanes/pixel, default
// caching loads/stores (R1 showed streaming hints regress).

#define B_DIM 32
#define H_DIM 128
#define W_DIM 128
#define C_DIM 64
#define OH 64
#define OW 64
#define LANES_PER_PIX 16
#define C4 (C_DIM / 4)            // 16 float4 per pixel

#define BLOCK 256
#define GRID 1024
#define TOTAL_THREADS (B_DIM * OH * OW * LANES_PER_PIX)   // 2,097,152
#define ITERS (TOTAL_THREADS / (BLOCK * GRID))            // 8

__global__ __launch_bounds__(BLOCK, 8)
void pos_maxpool2d_kernel(const float* __restrict__ x, float* __restrict__ out) {
    const int tid0   = blockIdx.x * BLOCK + threadIdx.x;
    const int stride = GRID * BLOCK;                      // 262,144

    const float4* __restrict__ xv = reinterpret_cast<const float4*>(x);
    float4* __restrict__ ov = reinterpret_cast<float4*>(out);

    #pragma unroll 2
    for (int it = 0; it < ITERS; ++it) {
        const int tid  = tid0 + it * stride;
        const int lane = tid & (LANES_PER_PIX - 1);
        const int op   = tid >> 4;            // output pixel index

        const int ow = op & (OW - 1);
        const int oh = (op >> 6) & (OH - 1);
        const int b  = op >> 12;

        const int base = ((b * H_DIM + 2 * oh) * W_DIM + 2 * ow) * C4;
        const int rs   = W_DIM * C4;

        const float4 v0 = xv[base + lane];
        const float4 v1 = xv[base + C4 + lane];
        const float4 v2 = xv[base + rs + lane];
        const float4 v3 = xv[base + rs + C4 + lane];

        float n0 = v0.x * v0.x + v0.y * v0.y + v0.z * v0.z + v0.w * v0.w;
        float n1 = v1.x * v1.x + v1.y * v1.y + v1.z * v1.z + v1.w * v1.w;
        float n2 = v2.x * v2.x + v2.y * v2.y + v2.z * v2.z + v2.w * v2.w;
        float n3 = v3.x * v3.x + v3.y * v3.y + v3.z * v3.z + v3.w * v3.w;

        // Butterfly reduction within each 16-lane group; all lanes end with
        // bitwise-identical sums.
        #pragma unroll
        for (int s = LANES_PER_PIX / 2; s > 0; s >>= 1) {
            n0 += __shfl_xor_sync(0xffffffffu, n0, s);
            n1 += __shfl_xor_sync(0xffffffffu, n1, s);
            n2 += __shfl_xor_sync(0xffffffffu, n2, s);
            n3 += __shfl_xor_sync(0xffffffffu, n3, s);
        }

        // First-occurrence argmax (strict > matches jnp.argmax tie-break).
        int   idx  = 0;
        float best = n0;
        if (n1 > best) { best = n1; idx = 1; }
        if (n2 > best) { best = n2; idx = 2; }
        if (n3 > best) { best = n3; idx = 3; }

        float4 w = v0;
        if (idx == 1) w = v1;
        if (idx == 2) w = v2;
        if (idx == 3) w = v3;

        ov[op * C4 + lane] = w;
    }
}

extern "C" void kernel_launch(void* const* d_in, const int* in_sizes, int n_in,
                              void* d_out, int out_size) {
    const float* x = (const float*)d_in[0];
    float* out = (float*)d_out;
    pos_maxpool2d_kernel<<<GRID, BLOCK>>>(x, out);
}